// round 2
// baseline (speedup 1.0000x reference)
#include <cuda_runtime.h>
#include <cuda_bf16.h>

// CholeskyMMNet: fused MLP (32->512->512->512->512->528) + per-row L@L^T.
// One CTA = 64 rows, 512 threads, activations resident in shared memory.
//
// Inputs (metadata order):
//  0: q     [65536,32]  f32
//  1: W_in  [32,512]    2: b_in [512]
//  3: W_h1  [512,512]   4: b_h1 [512]
//  5: W_h2  [512,512]   6: b_h2 [512]
//  7: W_out [512,512]   8: b_out[512]
//  9: W_o   [512,528]  10: b_o  [528]
// Output: M [65536,32,32] f32

#define TM 64          // rows per CTA
#define NT 512         // threads per CTA
#define KC 16          // k-chunk for streamed weight tiles
#define HDIM 512
#define NTRIL_COLS 528
#define QDIM 32
#define BIAS_F 2.0f

// shared layout (floats):
//  xs : [0, 32768)            64x512 activations
//  ws : [32768, 49152)        16384 floats (64KB) weight tile buffer
//  qs : [49152, 51200)        64x32 q tile
//  ps : [0, 33792)            64x528 L_params overlay (valid only after last GEMM)
#define SMEM_FLOATS (32768 + 16384 + 2048)
#define SMEM_BYTES  (SMEM_FLOATS * 4)

// Generic 512->512 layer: y = f(x @ W + b) (+ x), x in smem, W streamed.
template<bool RELU, bool RES>
__device__ __forceinline__ void layer512(float* __restrict__ xs,
                                         float* __restrict__ ws,
                                         const float* __restrict__ W,
                                         const float* __restrict__ b,
                                         int rowg, int colg, int tid)
{
    float acc[8][8];
    #pragma unroll
    for (int i = 0; i < 8; i++)
        #pragma unroll
        for (int j = 0; j < 8; j++) acc[i][j] = 0.f;

    for (int kt = 0; kt < HDIM; kt += KC) {
        // load W[kt..kt+16)[0..512) : 2048 float4, 4 per thread
        const float4* wg = (const float4*)(W + (size_t)kt * HDIM);
        float4* wsv = (float4*)ws;
        #pragma unroll
        for (int i = 0; i < 4; i++) wsv[tid + i * NT] = wg[tid + i * NT];
        __syncthreads();

        #pragma unroll
        for (int kk = 0; kk < KC; kk++) {
            float a[8], bb[8];
            #pragma unroll
            for (int i = 0; i < 8; i++) a[i] = xs[(rowg * 8 + i) * HDIM + kt + kk];
            #pragma unroll
            for (int j = 0; j < 8; j++) bb[j] = ws[kk * HDIM + colg + 64 * j];
            #pragma unroll
            for (int i = 0; i < 8; i++)
                #pragma unroll
                for (int j = 0; j < 8; j++) acc[i][j] = fmaf(a[i], bb[j], acc[i][j]);
        }
        __syncthreads();   // protects ws reload and (final iter) xs overwrite
    }

    #pragma unroll
    for (int j = 0; j < 8; j++) {
        int c = colg + 64 * j;
        float bv = __ldg(b + c);
        #pragma unroll
        for (int i = 0; i < 8; i++) {
            int r = rowg * 8 + i;
            float v = acc[i][j] + bv;
            if (RELU) v = fmaxf(v, 0.f);
            if (RES)  v += xs[r * HDIM + c];
            xs[r * HDIM + c] = v;
        }
    }
    __syncthreads();
}

__global__ void __launch_bounds__(NT)
cholesky_mmnet_kernel(const float* __restrict__ q,
                      const float* __restrict__ Win,  const float* __restrict__ bin,
                      const float* __restrict__ Wh1,  const float* __restrict__ bh1,
                      const float* __restrict__ Wh2,  const float* __restrict__ bh2,
                      const float* __restrict__ Wout, const float* __restrict__ bout,
                      const float* __restrict__ Wo,   const float* __restrict__ bo,
                      float* __restrict__ out)
{
    extern __shared__ float s[];
    float* xs = s;                  // [64][512]
    float* ws = s + 32768;          // [16384]
    float* qs = s + 32768 + 16384;  // [64][32]
    float* ps = s;                  // [64][528] overlay

    const int tid  = threadIdx.x;
    const int rowg = tid >> 6;      // 0..7
    const int colg = tid & 63;      // 0..63
    const int row0 = blockIdx.x * TM;

    // ---- load q tile (64x32 = 512 float4) ----
    {
        const float4* qg = (const float4*)(q + (size_t)row0 * QDIM);
        ((float4*)qs)[tid] = qg[tid];
    }

    // ---- layer 0: x = relu(q @ W_in + b_in), k = 32, W_in fully in ws ----
    {
        const float4* wg = (const float4*)Win;   // 4096 float4
        float4* wsv = (float4*)ws;
        #pragma unroll
        for (int i = 0; i < 8; i++) wsv[tid + i * NT] = wg[tid + i * NT];
        __syncthreads();

        float acc[8][8];
        #pragma unroll
        for (int i = 0; i < 8; i++)
            #pragma unroll
            for (int j = 0; j < 8; j++) acc[i][j] = 0.f;

        #pragma unroll
        for (int kk = 0; kk < QDIM; kk++) {
            float a[8], bb[8];
            #pragma unroll
            for (int i = 0; i < 8; i++) a[i] = qs[(rowg * 8 + i) * QDIM + kk];
            #pragma unroll
            for (int j = 0; j < 8; j++) bb[j] = ws[kk * HDIM + colg + 64 * j];
            #pragma unroll
            for (int i = 0; i < 8; i++)
                #pragma unroll
                for (int j = 0; j < 8; j++) acc[i][j] = fmaf(a[i], bb[j], acc[i][j]);
        }

        #pragma unroll
        for (int j = 0; j < 8; j++) {
            int c = colg + 64 * j;
            float bv = __ldg(bin + c);
            #pragma unroll
            for (int i = 0; i < 8; i++) {
                float v = fmaxf(acc[i][j] + bv, 0.f);
                xs[(rowg * 8 + i) * HDIM + c] = v;
            }
        }
        __syncthreads();
    }

    // ---- hidden layers with residual ----
    layer512<true, true>(xs, ws, Wh1, bh1, rowg, colg, tid);
    layer512<true, true>(xs, ws, Wh2, bh2, rowg, colg, tid);
    // ---- embed = x @ W_out + b_out (no relu, no residual) ----
    layer512<false, false>(xs, ws, Wout, bout, rowg, colg, tid);

    // ---- L_params = embed @ W_o + b_o  (cols = 528) ----
    {
        float acc[8][9];
        #pragma unroll
        for (int i = 0; i < 8; i++)
            #pragma unroll
            for (int j = 0; j < 9; j++) acc[i][j] = 0.f;

        const bool has9 = (colg < 16);   // col 512 + colg valid only for colg<16

        for (int kt = 0; kt < HDIM; kt += KC) {
            // load W_o[kt..kt+16)[0..528): 2112 float4
            const float4* wg = (const float4*)(Wo + (size_t)kt * NTRIL_COLS);
            float4* wsv = (float4*)ws;
            for (int i = tid; i < (KC * NTRIL_COLS) / 4; i += NT) wsv[i] = wg[i];
            __syncthreads();

            #pragma unroll
            for (int kk = 0; kk < KC; kk++) {
                float a[8], bb[9];
                #pragma unroll
                for (int i = 0; i < 8; i++) a[i] = xs[(rowg * 8 + i) * HDIM + kt + kk];
                #pragma unroll
                for (int j = 0; j < 8; j++) bb[j] = ws[kk * NTRIL_COLS + colg + 64 * j];
                bb[8] = has9 ? ws[kk * NTRIL_COLS + 512 + colg] : 0.f;
                #pragma unroll
                for (int i = 0; i < 8; i++)
                    #pragma unroll
                    for (int j = 0; j < 9; j++) acc[i][j] = fmaf(a[i], bb[j], acc[i][j]);
            }
            __syncthreads();   // all xs/ws reads done before overlay writes below
        }

        // write L_params into overlay ps [64][528] (overwrites xs — safe post-sync)
        #pragma unroll
        for (int j = 0; j < 8; j++) {
            int c = colg + 64 * j;
            float bv = __ldg(bo + c);
            #pragma unroll
            for (int i = 0; i < 8; i++)
                ps[(rowg * 8 + i) * NTRIL_COLS + c] = acc[i][j] + bv;
        }
        if (has9) {
            int c = 512 + colg;
            float bv = __ldg(bo + c);
            #pragma unroll
            for (int i = 0; i < 8; i++)
                ps[(rowg * 8 + i) * NTRIL_COLS + c] = acc[i][8] + bv;
        }
        __syncthreads();
    }

    // ---- M = L @ L^T per row ----
    // L[i][k] = ps[32 + i*(i-1)/2 + k] (k<i), ps[i]+BIAS (k==i), 0 (k>i)
    for (int idx = tid; idx < TM * QDIM * QDIM; idx += NT) {
        int r  = idx >> 10;
        int ij = idx & 1023;
        int i  = ij >> 5;
        int j  = ij & 31;
        const float* pr = ps + r * NTRIL_COLS;

        int mn = i < j ? i : j;
        int mx = i < j ? j : i;
        int bi = 32 + (i * (i - 1)) / 2;
        int bj = 32 + (j * (j - 1)) / 2;

        float sum = 0.f;
        for (int k = 0; k < mn; k++)
            sum = fmaf(pr[bi + k], pr[bj + k], sum);

        if (i == j) {
            float d = pr[i] + BIAS_F;
            sum = fmaf(d, d, sum);
        } else {
            // L[mx][mn] (strict lower) * (diag of mn)
            float lml = pr[32 + (mx * (mx - 1)) / 2 + mn];
            sum = fmaf(lml, pr[mn] + BIAS_F, sum);
        }
        out[(size_t)(row0 + r) * 1024 + ij] = sum;
    }
}

extern "C" void kernel_launch(void* const* d_in, const int* in_sizes, int n_in,
                              void* d_out, int out_size)
{
    const float* q    = (const float*)d_in[0];
    const float* Win  = (const float*)d_in[1];
    const float* bin  = (const float*)d_in[2];
    const float* Wh1  = (const float*)d_in[3];
    const float* bh1  = (const float*)d_in[4];
    const float* Wh2  = (const float*)d_in[5];
    const float* bh2  = (const float*)d_in[6];
    const float* Wout = (const float*)d_in[7];
    const float* bout = (const float*)d_in[8];
    const float* Wo   = (const float*)d_in[9];
    const float* bo   = (const float*)d_in[10];
    float* out = (float*)d_out;

    const int B = in_sizes[0] / QDIM;       // 65536
    const int grid = B / TM;                // 1024

    cudaFuncSetAttribute(cholesky_mmnet_kernel,
                         cudaFuncAttributeMaxDynamicSharedMemorySize, SMEM_BYTES);
    cholesky_mmnet_kernel<<<grid, NT, SMEM_BYTES>>>(
        q, Win, bin, Wh1, bh1, Wh2, bh2, Wout, bout, Wo, bo, out);
}

// round 3
// speedup vs baseline: 1.0016x; 1.0016x over previous
#include <cuda_runtime.h>
#include <cuda_bf16.h>

// CholeskyMMNet: fused MLP (32->512->512->512->512->528) + per-row L@L^T.
// One CTA = 64 rows, 512 threads, activations resident in shared memory.
//
// Inputs (metadata order):
//  0: q     [65536,32]  f32
//  1: W_in  [32,512]    2: b_in [512]
//  3: W_h1  [512,512]   4: b_h1 [512]
//  5: W_h2  [512,512]   6: b_h2 [512]
//  7: W_out [512,512]   8: b_out[512]
//  9: W_o   [512,528]  10: b_o  [528]
// Output: M [65536,32,32] f32

#define TM 64          // rows per CTA
#define NT 512         // threads per CTA
#define KC 16          // k-chunk for streamed weight tiles
#define HDIM 512
#define NTRIL_COLS 528
#define QDIM 32
#define BIAS_F 2.0f

// shared layout (floats):
//  xs : [0, 32768)            64x512 activations
//  ws : [32768, 49152)        16384 floats (64KB) weight tile buffer
//  qs : [49152, 51200)        64x32 q tile
//  ps : [0, 33792)            64x528 L_params overlay (valid only after last GEMM)
#define SMEM_FLOATS (32768 + 16384 + 2048)
#define SMEM_BYTES  (SMEM_FLOATS * 4)

// Generic 512->512 layer: y = f(x @ W + b) (+ x), x in smem, W streamed.
template<bool RELU, bool RES>
__device__ __forceinline__ void layer512(float* __restrict__ xs,
                                         float* __restrict__ ws,
                                         const float* __restrict__ W,
                                         const float* __restrict__ b,
                                         int rowg, int colg, int tid)
{
    float acc[8][8];
    #pragma unroll
    for (int i = 0; i < 8; i++)
        #pragma unroll
        for (int j = 0; j < 8; j++) acc[i][j] = 0.f;

    for (int kt = 0; kt < HDIM; kt += KC) {
        // load W[kt..kt+16)[0..512) : 2048 float4, 4 per thread
        const float4* wg = (const float4*)(W + (size_t)kt * HDIM);
        float4* wsv = (float4*)ws;
        #pragma unroll
        for (int i = 0; i < 4; i++) wsv[tid + i * NT] = wg[tid + i * NT];
        __syncthreads();

        #pragma unroll
        for (int kk = 0; kk < KC; kk++) {
            float a[8], bb[8];
            #pragma unroll
            for (int i = 0; i < 8; i++) a[i] = xs[(rowg * 8 + i) * HDIM + kt + kk];
            #pragma unroll
            for (int j = 0; j < 8; j++) bb[j] = ws[kk * HDIM + colg + 64 * j];
            #pragma unroll
            for (int i = 0; i < 8; i++)
                #pragma unroll
                for (int j = 0; j < 8; j++) acc[i][j] = fmaf(a[i], bb[j], acc[i][j]);
        }
        __syncthreads();   // protects ws reload and (final iter) xs overwrite
    }

    #pragma unroll
    for (int j = 0; j < 8; j++) {
        int c = colg + 64 * j;
        float bv = __ldg(b + c);
        #pragma unroll
        for (int i = 0; i < 8; i++) {
            int r = rowg * 8 + i;
            float v = acc[i][j] + bv;
            if (RELU) v = fmaxf(v, 0.f);
            if (RES)  v += xs[r * HDIM + c];
            xs[r * HDIM + c] = v;
        }
    }
    __syncthreads();
}

__global__ void __launch_bounds__(NT)
cholesky_mmnet_kernel(const float* __restrict__ q,
                      const float* __restrict__ Win,  const float* __restrict__ bin,
                      const float* __restrict__ Wh1,  const float* __restrict__ bh1,
                      const float* __restrict__ Wh2,  const float* __restrict__ bh2,
                      const float* __restrict__ Wout, const float* __restrict__ bout,
                      const float* __restrict__ Wo,   const float* __restrict__ bo,
                      float* __restrict__ out)
{
    extern __shared__ float s[];
    float* xs = s;                  // [64][512]
    float* ws = s + 32768;          // [16384]
    float* qs = s + 32768 + 16384;  // [64][32]
    float* ps = s;                  // [64][528] overlay

    const int tid  = threadIdx.x;
    const int rowg = tid >> 6;      // 0..7
    const int colg = tid & 63;      // 0..63
    const int row0 = blockIdx.x * TM;

    // ---- load q tile (64x32 = 512 float4) ----
    {
        const float4* qg = (const float4*)(q + (size_t)row0 * QDIM);
        ((float4*)qs)[tid] = qg[tid];
    }

    // ---- layer 0: x = relu(q @ W_in + b_in), k = 32, W_in fully in ws ----
    {
        const float4* wg = (const float4*)Win;   // 4096 float4
        float4* wsv = (float4*)ws;
        #pragma unroll
        for (int i = 0; i < 8; i++) wsv[tid + i * NT] = wg[tid + i * NT];
        __syncthreads();

        float acc[8][8];
        #pragma unroll
        for (int i = 0; i < 8; i++)
            #pragma unroll
            for (int j = 0; j < 8; j++) acc[i][j] = 0.f;

        #pragma unroll
        for (int kk = 0; kk < QDIM; kk++) {
            float a[8], bb[8];
            #pragma unroll
            for (int i = 0; i < 8; i++) a[i] = qs[(rowg * 8 + i) * QDIM + kk];
            #pragma unroll
            for (int j = 0; j < 8; j++) bb[j] = ws[kk * HDIM + colg + 64 * j];
            #pragma unroll
            for (int i = 0; i < 8; i++)
                #pragma unroll
                for (int j = 0; j < 8; j++) acc[i][j] = fmaf(a[i], bb[j], acc[i][j]);
        }

        #pragma unroll
        for (int j = 0; j < 8; j++) {
            int c = colg + 64 * j;
            float bv = __ldg(bin + c);
            #pragma unroll
            for (int i = 0; i < 8; i++) {
                float v = fmaxf(acc[i][j] + bv, 0.f);
                xs[(rowg * 8 + i) * HDIM + c] = v;
            }
        }
        __syncthreads();
    }

    // ---- hidden layers with residual ----
    layer512<true, true>(xs, ws, Wh1, bh1, rowg, colg, tid);
    layer512<true, true>(xs, ws, Wh2, bh2, rowg, colg, tid);
    // ---- embed = x @ W_out + b_out (no relu, no residual) ----
    layer512<false, false>(xs, ws, Wout, bout, rowg, colg, tid);

    // ---- L_params = embed @ W_o + b_o  (cols = 528) ----
    {
        float acc[8][9];
        #pragma unroll
        for (int i = 0; i < 8; i++)
            #pragma unroll
            for (int j = 0; j < 9; j++) acc[i][j] = 0.f;

        const bool has9 = (colg < 16);   // col 512 + colg valid only for colg<16

        for (int kt = 0; kt < HDIM; kt += KC) {
            // load W_o[kt..kt+16)[0..528): 2112 float4
            const float4* wg = (const float4*)(Wo + (size_t)kt * NTRIL_COLS);
            float4* wsv = (float4*)ws;
            for (int i = tid; i < (KC * NTRIL_COLS) / 4; i += NT) wsv[i] = wg[i];
            __syncthreads();

            #pragma unroll
            for (int kk = 0; kk < KC; kk++) {
                float a[8], bb[9];
                #pragma unroll
                for (int i = 0; i < 8; i++) a[i] = xs[(rowg * 8 + i) * HDIM + kt + kk];
                #pragma unroll
                for (int j = 0; j < 8; j++) bb[j] = ws[kk * NTRIL_COLS + colg + 64 * j];
                bb[8] = has9 ? ws[kk * NTRIL_COLS + 512 + colg] : 0.f;
                #pragma unroll
                for (int i = 0; i < 8; i++)
                    #pragma unroll
                    for (int j = 0; j < 9; j++) acc[i][j] = fmaf(a[i], bb[j], acc[i][j]);
            }
            __syncthreads();   // all xs/ws reads done before overlay writes below
        }

        // write L_params into overlay ps [64][528] (overwrites xs — safe post-sync)
        #pragma unroll
        for (int j = 0; j < 8; j++) {
            int c = colg + 64 * j;
            float bv = __ldg(bo + c);
            #pragma unroll
            for (int i = 0; i < 8; i++)
                ps[(rowg * 8 + i) * NTRIL_COLS + c] = acc[i][j] + bv;
        }
        if (has9) {
            int c = 512 + colg;
            float bv = __ldg(bo + c);
            #pragma unroll
            for (int i = 0; i < 8; i++)
                ps[(rowg * 8 + i) * NTRIL_COLS + c] = acc[i][8] + bv;
        }
        __syncthreads();
    }

    // ---- M = L @ L^T per row ----
    // L[i][k] = ps[32 + i*(i-1)/2 + k] (k<i), ps[i]+BIAS (k==i), 0 (k>i)
    for (int idx = tid; idx < TM * QDIM * QDIM; idx += NT) {
        int r  = idx >> 10;
        int ij = idx & 1023;
        int i  = ij >> 5;
        int j  = ij & 31;
        const float* pr = ps + r * NTRIL_COLS;

        int mn = i < j ? i : j;
        int mx = i < j ? j : i;
        int bi = 32 + (i * (i - 1)) / 2;
        int bj = 32 + (j * (j - 1)) / 2;

        float sum = 0.f;
        for (int k = 0; k < mn; k++)
            sum = fmaf(pr[bi + k], pr[bj + k], sum);

        if (i == j) {
            float d = pr[i] + BIAS_F;
            sum = fmaf(d, d, sum);
        } else {
            // L[mx][mn] (strict lower) * (diag of mn)
            float lml = pr[32 + (mx * (mx - 1)) / 2 + mn];
            sum = fmaf(lml, pr[mn] + BIAS_F, sum);
        }
        out[(size_t)(row0 + r) * 1024 + ij] = sum;
    }
}

extern "C" void kernel_launch(void* const* d_in, const int* in_sizes, int n_in,
                              void* d_out, int out_size)
{
    const float* q    = (const float*)d_in[0];
    const float* Win  = (const float*)d_in[1];
    const float* bin  = (const float*)d_in[2];
    const float* Wh1  = (const float*)d_in[3];
    const float* bh1  = (const float*)d_in[4];
    const float* Wh2  = (const float*)d_in[5];
    const float* bh2  = (const float*)d_in[6];
    const float* Wout = (const float*)d_in[7];
    const float* bout = (const float*)d_in[8];
    const float* Wo   = (const float*)d_in[9];
    const float* bo   = (const float*)d_in[10];
    float* out = (float*)d_out;

    const int B = in_sizes[0] / QDIM;       // 65536
    const int grid = B / TM;                // 1024

    cudaFuncSetAttribute(cholesky_mmnet_kernel,
                         cudaFuncAttributeMaxDynamicSharedMemorySize, SMEM_BYTES);
    cholesky_mmnet_kernel<<<grid, NT, SMEM_BYTES>>>(
        q, Win, bin, Wh1, bh1, Wh2, bh2, Wout, bout, Wo, bo, out);
}